// round 12
// baseline (speedup 1.0000x reference)
#include <cuda_runtime.h>
#include <math.h>
#include <mma.h>

using namespace nvcuda;

#define BB 8
#define SS 2048
#define KIN 128
#define NIN 256
#define NPROC 1024
#define KPROC 256
#define DM 1024

// ---------------- scratch (device globals; no allocation allowed) ----------------
__device__ float g_PWT[NIN * NPROC];
__device__ float g_Wg[BB * KIN * NPROC];
__device__ float g_part[BB * 16 * NPROC];
__device__ int   g_pidx[BB * KPROC];
__device__ float g_actsT[(size_t)BB * NPROC * SS]; // gelu acts, transposed, tf32-rounded
__device__ float g_Ptf[NPROC * DM];                // process_outputs, tf32-rounded

__device__ __forceinline__ float gelu_exact(float x) {
    return 0.5f * x * (1.0f + erff(x * 0.70710678118654752f));
}

// ---------------- K0: transpose process_weights [1024][256] -> PWT [256][1024] ----
__global__ void k_transpose(const float* __restrict__ pw) {
    __shared__ float t[32][33];
    int x = blockIdx.x * 32 + threadIdx.x;
    int y = blockIdx.y * 32 + threadIdx.y;
    #pragma unroll
    for (int i = 0; i < 32; i += 8)
        t[threadIdx.y + i][threadIdx.x] = pw[(y + i) * NIN + x];
    __syncthreads();
    int x2 = blockIdx.y * 32 + threadIdx.x;
    int y2 = blockIdx.x * 32 + threadIdx.y;
    #pragma unroll
    for (int i = 0; i < 32; i += 8)
        g_PWT[(y2 + i) * NPROC + x2] = t[threadIdx.x][threadIdx.y + i];
}

// ---------------- K1: gather Wg[b][k][:] = PWT[input_idx[b][k]][:] -----------------
__global__ void k_gather_wg(const int* __restrict__ iidx) {
    int b = blockIdx.x / KIN;
    int k = blockIdx.x % KIN;
    int c = iidx[b * KIN + k];
    const float4* src = (const float4*)&g_PWT[(size_t)c * NPROC];
    float4* dst = (float4*)&g_Wg[((size_t)b * KIN + k) * NPROC];
    dst[threadIdx.x] = src[threadIdx.x];
}

// ---------------- K1b: pre-round process_outputs to tf32 bit patterns --------------
__global__ void k_round_P(const float* __restrict__ P) {
    int idx = blockIdx.x * blockDim.x + threadIdx.x;
    float4 v = ((const float4*)P)[idx];
    v.x = wmma::__float_to_tf32(v.x); v.y = wmma::__float_to_tf32(v.y);
    v.z = wmma::__float_to_tf32(v.z); v.w = wmma::__float_to_tf32(v.w);
    ((float4*)g_Ptf)[idx] = v;
}

// ---------------- K2: GEMM1 + gelu (SIMT fp32), K-tile 64: 2 load/barrier phases ---
// 128x128 tile, 8x8 microtile; inner code identical to R8 -> regs stay 128,
// k order strictly sequential -> scores bit-identical.
// dynamic smem: As[64][128] + Bs[64][128] = 64 KB (2 CTAs/SM).
__global__ __launch_bounds__(256) void k_scores(const float* __restrict__ X) {
    extern __shared__ float k2sm[];
    float* As_ = k2sm;                 // [64][128]  As_[k*128 + m]
    float* Bs_ = k2sm + 64 * 128;      // [64][128]  Bs_[k*128 + n]
    int b = blockIdx.z;
    int m0 = blockIdx.x * 128;
    int n0 = blockIdx.y * 128;
    int tid = threadIdx.x;
    int tx = tid & 15, ty = tid >> 4;
    const float* A = X + (size_t)b * SS * KIN;
    const float* Bm = g_Wg + (size_t)b * KIN * NPROC;
    float acc[8][8];
    #pragma unroll
    for (int i = 0; i < 8; i++)
        #pragma unroll
        for (int j = 0; j < 8; j++) acc[i][j] = 0.f;

    for (int kc = 0; kc < KIN; kc += 64) {
        // A tile: 128 m x 64 k -> As[k][m]  (2048 float4, 8 per thread)
        #pragma unroll
        for (int it = 0; it < 8; it++) {
            int idx = tid + it * 256;
            int row = idx >> 4, c4 = (idx & 15) * 4;
            float4 v = *(const float4*)&A[(m0 + row) * KIN + kc + c4];
            As_[(c4 + 0) * 128 + row] = v.x; As_[(c4 + 1) * 128 + row] = v.y;
            As_[(c4 + 2) * 128 + row] = v.z; As_[(c4 + 3) * 128 + row] = v.w;
        }
        // B tile: 64 k x 128 n (2048 float4, 8 per thread)
        #pragma unroll
        for (int it = 0; it < 8; it++) {
            int idx = tid + it * 256;
            int row = idx >> 5, c4 = (idx & 31) * 4;
            *(float4*)&Bs_[row * 128 + c4] =
                *(const float4*)&Bm[(kc + row) * NPROC + n0 + c4];
        }
        __syncthreads();
        #pragma unroll 8
        for (int kk = 0; kk < 64; kk++) {
            float a[8], bv[8];
            #pragma unroll
            for (int i = 0; i < 8; i++) a[i] = As_[kk * 128 + ty * 8 + i];
            *(float4*)&bv[0] = *(const float4*)&Bs_[kk * 128 + tx * 4];
            *(float4*)&bv[4] = *(const float4*)&Bs_[kk * 128 + 64 + tx * 4];
            #pragma unroll
            for (int i = 0; i < 8; i++)
                #pragma unroll
                for (int j = 0; j < 8; j++) acc[i][j] += a[i] * bv[j];
        }
        __syncthreads();
    }
    float cs[8];
    #pragma unroll
    for (int j = 0; j < 8; j++) {
        float gv[8];
        float s = 0.f;
        #pragma unroll
        for (int i = 0; i < 8; i++) { gv[i] = gelu_exact(acc[i][j]); s += gv[i]; }
        cs[j] = s;
        int ncol = (j < 4) ? (tx * 4 + j) : (64 + tx * 4 + (j - 4));
        int n = n0 + ncol;
        float* dst = &g_actsT[((size_t)b * NPROC + n) * SS + m0 + ty * 8];
        *(float4*)dst = make_float4(
            wmma::__float_to_tf32(gv[0]), wmma::__float_to_tf32(gv[1]),
            wmma::__float_to_tf32(gv[2]), wmma::__float_to_tf32(gv[3]));
        *(float4*)(dst + 4) = make_float4(
            wmma::__float_to_tf32(gv[4]), wmma::__float_to_tf32(gv[5]),
            wmma::__float_to_tf32(gv[6]), wmma::__float_to_tf32(gv[7]));
    }
    __syncthreads();
    #pragma unroll
    for (int j = 0; j < 8; j++) {
        int ncol = (j < 4) ? (tx * 4 + j) : (64 + tx * 4 + (j - 4));
        k2sm[ty * 128 + ncol] = cs[j];
    }
    __syncthreads();
    if (tid < 128) {
        float s = 0.f;
        #pragma unroll
        for (int r = 0; r < 16; r++) s += k2sm[r * 128 + tid];
        g_part[((size_t)b * 16 + blockIdx.x) * NPROC + n0 + tid] = s;
    }
}

// ---------------- K4: per-batch reduce + bitonic top-256 of 1024 -------------------
__global__ __launch_bounds__(512) void k_topk() {
    __shared__ float sv[NPROC];
    __shared__ int   si[NPROC];
    int b = blockIdx.x;
    int tid = threadIdx.x;
    for (int t = tid; t < NPROC; t += 512) {
        float s = 0.f;
        #pragma unroll
        for (int r = 0; r < 16; r++) s += g_part[((size_t)b * 16 + r) * NPROC + t];
        sv[t] = s; si[t] = t;
    }
    __syncthreads();
    for (int k = 2; k <= NPROC; k <<= 1) {
        for (int j = k >> 1; j > 0; j >>= 1) {
            int i = ((tid & ~(j - 1)) << 1) | (tid & (j - 1));
            int ixj = i | j;
            bool desc = ((i & k) == 0);
            float v1 = sv[i], v2 = sv[ixj];
            if ((v1 < v2) == desc) {
                sv[i] = v2; sv[ixj] = v1;
                int tmp = si[i]; si[i] = si[ixj]; si[ixj] = tmp;
            }
            __syncthreads();
        }
    }
    if (tid < KPROC) g_pidx[b * KPROC + tid] = si[tid];
}

// ---------------- K6: out = actsT_sel^T @ Ptf_sel — TF32 TC (R8 measured-best) -----
// 128 threads = 4 warps (2x2), warp tile 64x64; K-tile 32; 2-stage cp.async
// double buffer (69632 B -> 2 CTAs/SM).
#define K6_STAGE_F 8704              // floats per stage: As 32*136 + Bs 32*136
__device__ __forceinline__ void k6_issue_stage(float* dsm, int s, int kc,
                                               const float* AT, const int* pidx,
                                               int m0, int n0, int tid) {
    float* As_ = dsm + s * K6_STAGE_F;
    float* Bs_ = As_ + 4352;
    #pragma unroll
    for (int it = 0; it < 8; it++) {
        int idx = tid + it * 128;
        int row = idx >> 5, c4 = (idx & 31) * 4;
        int nr = pidx[kc + row];
        unsigned dst = (unsigned)__cvta_generic_to_shared(&As_[row * 136 + c4]);
        const float* src = &AT[(size_t)nr * SS + m0 + c4];
        asm volatile("cp.async.cg.shared.global [%0], [%1], 16;\n" :: "r"(dst), "l"(src));
    }
    #pragma unroll
    for (int it = 0; it < 8; it++) {
        int idx = tid + it * 128;
        int row = idx >> 5, c4 = (idx & 31) * 4;
        int nr = pidx[kc + row];
        unsigned dst = (unsigned)__cvta_generic_to_shared(&Bs_[row * 136 + c4]);
        const float* src = &g_Ptf[(size_t)nr * DM + n0 + c4];
        asm volatile("cp.async.cg.shared.global [%0], [%1], 16;\n" :: "r"(dst), "l"(src));
    }
    asm volatile("cp.async.commit_group;\n" ::);
}

__global__ __launch_bounds__(128) void k_out_tc(float* __restrict__ out) {
    extern __shared__ float dsm[];
    int b = blockIdx.z;
    int m0 = blockIdx.x * 128;
    int n0 = blockIdx.y * 128;
    int tid = threadIdx.x;
    int wid = tid >> 5;
    int wm = wid & 1;
    int wn = wid >> 1;
    const float* AT = g_actsT + (size_t)b * NPROC * SS;
    const int* pidx = g_pidx + b * KPROC;

    wmma::fragment<wmma::accumulator, 16, 16, 8, float> acc[4][4];
    #pragma unroll
    for (int i = 0; i < 4; i++)
        #pragma unroll
        for (int j = 0; j < 4; j++) wmma::fill_fragment(acc[i][j], 0.0f);

    k6_issue_stage(dsm, 0, 0, AT, pidx, m0, n0, tid);
    k6_issue_stage(dsm, 1, 32, AT, pidx, m0, n0, tid);

    #pragma unroll
    for (int t = 0; t < 8; t++) {
        if (t < 7) asm volatile("cp.async.wait_group 1;\n" ::);
        else       asm volatile("cp.async.wait_group 0;\n" ::);
        __syncthreads();
        int s = t & 1;
        float* As_ = dsm + s * K6_STAGE_F;
        float* Bs_ = As_ + 4352;
        #pragma unroll
        for (int ks = 0; ks < 4; ks++) {
            wmma::fragment<wmma::matrix_a, 16, 16, 8, wmma::precision::tf32,
                           wmma::col_major> af[4];
            wmma::fragment<wmma::matrix_b, 16, 16, 8, wmma::precision::tf32,
                           wmma::row_major> bf[4];
            #pragma unroll
            for (int i = 0; i < 4; i++)
                wmma::load_matrix_sync(af[i], &As_[(ks * 8) * 136 + wm * 64 + i * 16], 136);
            #pragma unroll
            for (int j = 0; j < 4; j++)
                wmma::load_matrix_sync(bf[j], &Bs_[(ks * 8) * 136 + wn * 64 + j * 16], 136);
            #pragma unroll
            for (int i = 0; i < 4; i++)
                #pragma unroll
                for (int j = 0; j < 4; j++)
                    wmma::mma_sync(acc[i][j], af[i], bf[j], acc[i][j]);
        }
        __syncthreads();
        if (t + 2 < 8)
            k6_issue_stage(dsm, s, (t + 2) * 32, AT, pidx, m0, n0, tid);
    }
    #pragma unroll
    for (int i = 0; i < 4; i++)
        #pragma unroll
        for (int j = 0; j < 4; j++) {
            float* dst = out + ((size_t)(b * SS + m0 + wm * 64 + i * 16)) * DM
                             + n0 + wn * 64 + j * 16;
            wmma::store_matrix_sync(dst, acc[i][j], DM, wmma::mem_row_major);
        }
}

// ---------------- launch -----------------------------------------------------------
extern "C" void kernel_launch(void* const* d_in, const int* in_sizes, int n_in,
                              void* d_out, int out_size) {
    const float* X    = (const float*)d_in[0];   // [8,2048,128]
    const float* PW   = (const float*)d_in[1];   // [1024,256]
    const float* PO   = (const float*)d_in[2];   // [1024,1024]
    const int*   IIDX = (const int*)d_in[3];     // [8,128]

    cudaFuncSetAttribute(k_out_tc, cudaFuncAttributeMaxDynamicSharedMemorySize,
                         2 * K6_STAGE_F * 4);
    cudaFuncSetAttribute(k_scores, cudaFuncAttributeMaxDynamicSharedMemorySize,
                         2 * 64 * 128 * 4);

    k_transpose<<<dim3(NIN / 32, NPROC / 32), dim3(32, 8)>>>(PW);
    k_gather_wg<<<BB * KIN, 256>>>(IIDX);
    k_round_P<<<(NPROC * DM / 4) / 256, 256>>>(PO);
    k_scores<<<dim3(16, 8, BB), 256, 2 * 64 * 128 * 4>>>(X);
    k_topk<<<BB, 512>>>();
    k_out_tc<<<dim3(16, 8, BB), 128, 2 * K6_STAGE_F * 4>>>((float*)d_out);
}

// round 13
// speedup vs baseline: 1.1104x; 1.1104x over previous
#include <cuda_runtime.h>
#include <math.h>
#include <mma.h>

using namespace nvcuda;

#define BB 8
#define SS 2048
#define KIN 128
#define NIN 256
#define NPROC 1024
#define KPROC 256
#define DM 1024

// ---------------- scratch (device globals; no allocation allowed) ----------------
__device__ float g_PWT[NIN * NPROC];
__device__ float g_Wg[BB * KIN * NPROC];
__device__ float g_part[BB * 16 * NPROC];
__device__ int   g_pidx[BB * KPROC];
__device__ float g_actsT[(size_t)BB * NPROC * SS]; // gelu acts, transposed, tf32-rounded
__device__ float g_Ptf[NPROC * DM];                // process_outputs, tf32-rounded

__device__ __forceinline__ float gelu_exact(float x) {
    return 0.5f * x * (1.0f + erff(x * 0.70710678118654752f));
}

// ---------------- K0: transpose process_weights [1024][256] -> PWT [256][1024] ----
__global__ void k_transpose(const float* __restrict__ pw) {
    __shared__ float t[32][33];
    int x = blockIdx.x * 32 + threadIdx.x;
    int y = blockIdx.y * 32 + threadIdx.y;
    #pragma unroll
    for (int i = 0; i < 32; i += 8)
        t[threadIdx.y + i][threadIdx.x] = pw[(y + i) * NIN + x];
    __syncthreads();
    int x2 = blockIdx.y * 32 + threadIdx.x;
    int y2 = blockIdx.x * 32 + threadIdx.y;
    #pragma unroll
    for (int i = 0; i < 32; i += 8)
        g_PWT[(y2 + i) * NPROC + x2] = t[threadIdx.x][threadIdx.y + i];
}

// ---------------- K1: gather Wg[b][k][:] = PWT[input_idx[b][k]][:] -----------------
__global__ void k_gather_wg(const int* __restrict__ iidx) {
    int b = blockIdx.x / KIN;
    int k = blockIdx.x % KIN;
    int c = iidx[b * KIN + k];
    const float4* src = (const float4*)&g_PWT[(size_t)c * NPROC];
    float4* dst = (float4*)&g_Wg[((size_t)b * KIN + k) * NPROC];
    dst[threadIdx.x] = src[threadIdx.x];
}

// ---------------- K1b: pre-round process_outputs to tf32 bit patterns --------------
__global__ void k_round_P(const float* __restrict__ P) {
    int idx = blockIdx.x * blockDim.x + threadIdx.x;
    float4 v = ((const float4*)P)[idx];
    v.x = wmma::__float_to_tf32(v.x); v.y = wmma::__float_to_tf32(v.y);
    v.z = wmma::__float_to_tf32(v.z); v.w = wmma::__float_to_tf32(v.w);
    ((float4*)g_Ptf)[idx] = v;
}

// ---------------- K2: GEMM1 + gelu (SIMT fp32, R8 measured-best; DO NOT TOUCH) -----
// 128x128 tile, 8x8 microtile, K-tile 32, static smem, regs=128 -> 2 CTAs/SM.
__global__ __launch_bounds__(256) void k_scores(const float* __restrict__ X) {
    __shared__ float As[32][128];
    __shared__ float Bs[32][128];
    int b = blockIdx.z;
    int m0 = blockIdx.x * 128;
    int n0 = blockIdx.y * 128;
    int tid = threadIdx.x;
    int tx = tid & 15, ty = tid >> 4;
    const float* A = X + (size_t)b * SS * KIN;
    const float* Bm = g_Wg + (size_t)b * KIN * NPROC;
    float acc[8][8];
    #pragma unroll
    for (int i = 0; i < 8; i++)
        #pragma unroll
        for (int j = 0; j < 8; j++) acc[i][j] = 0.f;

    for (int kc = 0; kc < KIN; kc += 32) {
        #pragma unroll
        for (int it = 0; it < 4; it++) {
            int idx = tid + it * 256;
            int row = idx >> 3, c4 = (idx & 7) * 4;
            float4 v = *(const float4*)&A[(m0 + row) * KIN + kc + c4];
            As[c4 + 0][row] = v.x; As[c4 + 1][row] = v.y;
            As[c4 + 2][row] = v.z; As[c4 + 3][row] = v.w;
        }
        #pragma unroll
        for (int it = 0; it < 4; it++) {
            int idx = tid + it * 256;
            int row = idx >> 5, c4 = (idx & 31) * 4;
            *(float4*)&Bs[row][c4] =
                *(const float4*)&Bm[(kc + row) * NPROC + n0 + c4];
        }
        __syncthreads();
        #pragma unroll
        for (int kk = 0; kk < 32; kk++) {
            float a[8], bv[8];
            #pragma unroll
            for (int i = 0; i < 8; i++) a[i] = As[kk][ty * 8 + i];
            *(float4*)&bv[0] = *(const float4*)&Bs[kk][tx * 4];
            *(float4*)&bv[4] = *(const float4*)&Bs[kk][64 + tx * 4];
            #pragma unroll
            for (int i = 0; i < 8; i++)
                #pragma unroll
                for (int j = 0; j < 8; j++) acc[i][j] += a[i] * bv[j];
        }
        __syncthreads();
    }
    float cs[8];
    #pragma unroll
    for (int j = 0; j < 8; j++) {
        float gv[8];
        float s = 0.f;
        #pragma unroll
        for (int i = 0; i < 8; i++) { gv[i] = gelu_exact(acc[i][j]); s += gv[i]; }
        cs[j] = s;
        int ncol = (j < 4) ? (tx * 4 + j) : (64 + tx * 4 + (j - 4));
        int n = n0 + ncol;
        float* dst = &g_actsT[((size_t)b * NPROC + n) * SS + m0 + ty * 8];
        *(float4*)dst = make_float4(
            wmma::__float_to_tf32(gv[0]), wmma::__float_to_tf32(gv[1]),
            wmma::__float_to_tf32(gv[2]), wmma::__float_to_tf32(gv[3]));
        *(float4*)(dst + 4) = make_float4(
            wmma::__float_to_tf32(gv[4]), wmma::__float_to_tf32(gv[5]),
            wmma::__float_to_tf32(gv[6]), wmma::__float_to_tf32(gv[7]));
    }
    __syncthreads();
    #pragma unroll
    for (int j = 0; j < 8; j++) {
        int ncol = (j < 4) ? (tx * 4 + j) : (64 + tx * 4 + (j - 4));
        As[ty][ncol] = cs[j];
    }
    __syncthreads();
    if (tid < 128) {
        float s = 0.f;
        #pragma unroll
        for (int r = 0; r < 16; r++) s += As[r][tid];
        g_part[((size_t)b * 16 + blockIdx.x) * NPROC + n0 + tid] = s;
    }
}

// ---------------- K4: per-batch reduce + bitonic top-256 of 1024 -------------------
__global__ __launch_bounds__(512) void k_topk() {
    __shared__ float sv[NPROC];
    __shared__ int   si[NPROC];
    int b = blockIdx.x;
    int tid = threadIdx.x;
    for (int t = tid; t < NPROC; t += 512) {
        float s = 0.f;
        #pragma unroll
        for (int r = 0; r < 16; r++) s += g_part[((size_t)b * 16 + r) * NPROC + t];
        sv[t] = s; si[t] = t;
    }
    __syncthreads();
    for (int k = 2; k <= NPROC; k <<= 1) {
        for (int j = k >> 1; j > 0; j >>= 1) {
            int i = ((tid & ~(j - 1)) << 1) | (tid & (j - 1));
            int ixj = i | j;
            bool desc = ((i & k) == 0);
            float v1 = sv[i], v2 = sv[ixj];
            if ((v1 < v2) == desc) {
                sv[i] = v2; sv[ixj] = v1;
                int tmp = si[i]; si[i] = si[ixj]; si[ixj] = tmp;
            }
            __syncthreads();
        }
    }
    if (tid < KPROC) g_pidx[b * KPROC + tid] = si[tid];
}

// ---------------- K6: out = actsT_sel^T @ Ptf_sel — TF32 TC ------------------------
// R8 tile (M128 x N128, 128 threads, 4 warps 2x2, warp tile 64x64, K-tile 32)
// + 3-stage cp.async ring with ONE __syncthreads per stage.
// smem 3 x 34816 B = 104448 B -> 2 CTAs/SM.
#define K6_STAGE_F 8704              // floats per stage: As 32*136 + Bs 32*136
__device__ __forceinline__ void k6_issue_stage(float* dsm, int s, int kc,
                                               const float* AT, const int* pidx,
                                               int m0, int n0, int tid) {
    float* As_ = dsm + s * K6_STAGE_F;
    float* Bs_ = As_ + 4352;
    #pragma unroll
    for (int it = 0; it < 8; it++) {
        int idx = tid + it * 128;
        int row = idx >> 5, c4 = (idx & 31) * 4;
        int nr = pidx[kc + row];
        unsigned dst = (unsigned)__cvta_generic_to_shared(&As_[row * 136 + c4]);
        const float* src = &AT[(size_t)nr * SS + m0 + c4];
        asm volatile("cp.async.cg.shared.global [%0], [%1], 16;\n" :: "r"(dst), "l"(src));
    }
    #pragma unroll
    for (int it = 0; it < 8; it++) {
        int idx = tid + it * 128;
        int row = idx >> 5, c4 = (idx & 31) * 4;
        int nr = pidx[kc + row];
        unsigned dst = (unsigned)__cvta_generic_to_shared(&Bs_[row * 136 + c4]);
        const float* src = &g_Ptf[(size_t)nr * DM + n0 + c4];
        asm volatile("cp.async.cg.shared.global [%0], [%1], 16;\n" :: "r"(dst), "l"(src));
    }
    asm volatile("cp.async.commit_group;\n" ::);
}

__global__ __launch_bounds__(128) void k_out_tc(float* __restrict__ out) {
    extern __shared__ float dsm[];
    int b = blockIdx.z;
    int m0 = blockIdx.x * 128;
    int n0 = blockIdx.y * 128;
    int tid = threadIdx.x;
    int wid = tid >> 5;
    int wm = wid & 1;
    int wn = wid >> 1;
    const float* AT = g_actsT + (size_t)b * NPROC * SS;
    const int* pidx = g_pidx + b * KPROC;

    wmma::fragment<wmma::accumulator, 16, 16, 8, float> acc[4][4];
    #pragma unroll
    for (int i = 0; i < 4; i++)
        #pragma unroll
        for (int j = 0; j < 4; j++) wmma::fill_fragment(acc[i][j], 0.0f);

    k6_issue_stage(dsm, 0, 0, AT, pidx, m0, n0, tid);
    k6_issue_stage(dsm, 1, 32, AT, pidx, m0, n0, tid);

    #pragma unroll
    for (int t = 0; t < 8; t++) {
        // ensure stage t landed (t+1 may still be in flight)
        if (t < 7) asm volatile("cp.async.wait_group 1;\n" ::);
        else       asm volatile("cp.async.wait_group 0;\n" ::);
        __syncthreads();   // stage t visible; all warps finished compute t-1
        // refill the buffer compute t-1 just vacated
        if (t + 2 < 8)
            k6_issue_stage(dsm, (t + 2) % 3, (t + 2) * 32, AT, pidx, m0, n0, tid);
        float* As_ = dsm + (t % 3) * K6_STAGE_F;
        float* Bs_ = As_ + 4352;
        #pragma unroll
        for (int ks = 0; ks < 4; ks++) {
            wmma::fragment<wmma::matrix_a, 16, 16, 8, wmma::precision::tf32,
                           wmma::col_major> af[4];
            wmma::fragment<wmma::matrix_b, 16, 16, 8, wmma::precision::tf32,
                           wmma::row_major> bf[4];
            #pragma unroll
            for (int i = 0; i < 4; i++)
                wmma::load_matrix_sync(af[i], &As_[(ks * 8) * 136 + wm * 64 + i * 16], 136);
            #pragma unroll
            for (int j = 0; j < 4; j++)
                wmma::load_matrix_sync(bf[j], &Bs_[(ks * 8) * 136 + wn * 64 + j * 16], 136);
            #pragma unroll
            for (int i = 0; i < 4; i++)
                #pragma unroll
                for (int j = 0; j < 4; j++)
                    wmma::mma_sync(acc[i][j], af[i], bf[j], acc[i][j]);
        }
    }
    #pragma unroll
    for (int i = 0; i < 4; i++)
        #pragma unroll
        for (int j = 0; j < 4; j++) {
            float* dst = out + ((size_t)(b * SS + m0 + wm * 64 + i * 16)) * DM
                             + n0 + wn * 64 + j * 16;
            wmma::store_matrix_sync(dst, acc[i][j], DM, wmma::mem_row_major);
        }
}

// ---------------- launch -----------------------------------------------------------
extern "C" void kernel_launch(void* const* d_in, const int* in_sizes, int n_in,
                              void* d_out, int out_size) {
    const float* X    = (const float*)d_in[0];   // [8,2048,128]
    const float* PW   = (const float*)d_in[1];   // [1024,256]
    const float* PO   = (const float*)d_in[2];   // [1024,1024]
    const int*   IIDX = (const int*)d_in[3];     // [8,128]

    cudaFuncSetAttribute(k_out_tc, cudaFuncAttributeMaxDynamicSharedMemorySize,
                         3 * K6_STAGE_F * 4);

    k_transpose<<<dim3(NIN / 32, NPROC / 32), dim3(32, 8)>>>(PW);
    k_gather_wg<<<BB * KIN, 256>>>(IIDX);
    k_round_P<<<(NPROC * DM / 4) / 256, 256>>>(PO);
    k_scores<<<dim3(16, 8, BB), 256>>>(X);
    k_topk<<<BB, 512>>>();
    k_out_tc<<<dim3(16, 8, BB), 128, 3 * K6_STAGE_F * 4>>>((float*)d_out);
}

// round 14
// speedup vs baseline: 1.1275x; 1.0154x over previous
#include <cuda_runtime.h>
#include <math.h>
#include <mma.h>

using namespace nvcuda;

#define BB 8
#define SS 2048
#define KIN 128
#define NIN 256
#define NPROC 1024
#define KPROC 256
#define DM 1024

// ---------------- scratch (device globals; no allocation allowed) ----------------
__device__ float g_PWT[NIN * NPROC];
__device__ float g_Wg[BB * KIN * NPROC];
__device__ float g_part[BB * 16 * NPROC];
__device__ int   g_pidx[BB * KPROC];
__device__ float g_actsT[(size_t)BB * NPROC * SS]; // gelu acts, transposed, tf32-rounded
__device__ float g_Ptf[NPROC * DM];                // process_outputs, tf32-rounded

__device__ __forceinline__ float gelu_exact(float x) {
    return 0.5f * x * (1.0f + erff(x * 0.70710678118654752f));
}

// ---- packed dual-fp32 helpers (sm_100a f32x2; per-lane fp32 RN => bit-identical) --
__device__ __forceinline__ unsigned long long pk2(float lo, float hi) {
    unsigned long long r;
    asm("mov.b64 %0, {%1, %2};" : "=l"(r) : "f"(lo), "f"(hi));
    return r;
}
__device__ __forceinline__ void upk2(float& lo, float& hi, unsigned long long v) {
    asm("mov.b64 {%0, %1}, %2;" : "=f"(lo), "=f"(hi) : "l"(v));
}
__device__ __forceinline__ void ffma2(unsigned long long& d,
                                      unsigned long long a, unsigned long long b) {
    asm("fma.rn.f32x2 %0, %1, %2, %0;" : "+l"(d) : "l"(a), "l"(b));
}

// ---------------- K0: transpose process_weights [1024][256] -> PWT [256][1024] ----
__global__ void k_transpose(const float* __restrict__ pw) {
    __shared__ float t[32][33];
    int x = blockIdx.x * 32 + threadIdx.x;
    int y = blockIdx.y * 32 + threadIdx.y;
    #pragma unroll
    for (int i = 0; i < 32; i += 8)
        t[threadIdx.y + i][threadIdx.x] = pw[(y + i) * NIN + x];
    __syncthreads();
    int x2 = blockIdx.y * 32 + threadIdx.x;
    int y2 = blockIdx.x * 32 + threadIdx.y;
    #pragma unroll
    for (int i = 0; i < 32; i += 8)
        g_PWT[(y2 + i) * NPROC + x2] = t[threadIdx.x][threadIdx.y + i];
}

// ---------------- K1: gather Wg[b][k][:] = PWT[input_idx[b][k]][:] -----------------
__global__ void k_gather_wg(const int* __restrict__ iidx) {
    int b = blockIdx.x / KIN;
    int k = blockIdx.x % KIN;
    int c = iidx[b * KIN + k];
    const float4* src = (const float4*)&g_PWT[(size_t)c * NPROC];
    float4* dst = (float4*)&g_Wg[((size_t)b * KIN + k) * NPROC];
    dst[threadIdx.x] = src[threadIdx.x];
}

// ---------------- K1b: pre-round process_outputs to tf32 bit patterns --------------
__global__ void k_round_P(const float* __restrict__ P) {
    int idx = blockIdx.x * blockDim.x + threadIdx.x;
    float4 v = ((const float4*)P)[idx];
    v.x = wmma::__float_to_tf32(v.x); v.y = wmma::__float_to_tf32(v.y);
    v.z = wmma::__float_to_tf32(v.z); v.w = wmma::__float_to_tf32(v.w);
    ((float4*)g_Ptf)[idx] = v;
}

// ---------------- K2: GEMM1 + gelu — SIMT with packed f32x2 FMA --------------------
// 128x128 tile, 8x8 microtile, K-tile 32; inner loop: 32 FFMA2 instead of 64 FFMA.
// Per-lane fp32 RN, same k order -> scores bit-identical to all prior rounds.
__global__ __launch_bounds__(256) void k_scores(const float* __restrict__ X) {
    __shared__ float As[32][128];
    __shared__ float Bs[32][128];
    int b = blockIdx.z;
    int m0 = blockIdx.x * 128;
    int n0 = blockIdx.y * 128;
    int tid = threadIdx.x;
    int tx = tid & 15, ty = tid >> 4;
    const float* A = X + (size_t)b * SS * KIN;
    const float* Bm = g_Wg + (size_t)b * KIN * NPROC;
    unsigned long long acc2[8][4];   // lanes: (j=2q, j=2q+1)
    #pragma unroll
    for (int i = 0; i < 8; i++)
        #pragma unroll
        for (int q = 0; q < 4; q++) acc2[i][q] = 0ULL;   // (0.0f, 0.0f)

    for (int kc = 0; kc < KIN; kc += 32) {
        #pragma unroll
        for (int it = 0; it < 4; it++) {
            int idx = tid + it * 256;
            int row = idx >> 3, c4 = (idx & 7) * 4;
            float4 v = *(const float4*)&A[(m0 + row) * KIN + kc + c4];
            As[c4 + 0][row] = v.x; As[c4 + 1][row] = v.y;
            As[c4 + 2][row] = v.z; As[c4 + 3][row] = v.w;
        }
        #pragma unroll
        for (int it = 0; it < 4; it++) {
            int idx = tid + it * 256;
            int row = idx >> 5, c4 = (idx & 31) * 4;
            *(float4*)&Bs[row][c4] =
                *(const float4*)&Bm[(kc + row) * NPROC + n0 + c4];
        }
        __syncthreads();
        #pragma unroll
        for (int kk = 0; kk < 32; kk++) {
            float a[8], bv[8];
            #pragma unroll
            for (int i = 0; i < 8; i++) a[i] = As[kk][ty * 8 + i];
            *(float4*)&bv[0] = *(const float4*)&Bs[kk][tx * 4];
            *(float4*)&bv[4] = *(const float4*)&Bs[kk][64 + tx * 4];
            unsigned long long bv2[4];
            #pragma unroll
            for (int q = 0; q < 4; q++) bv2[q] = pk2(bv[2 * q], bv[2 * q + 1]);
            #pragma unroll
            for (int i = 0; i < 8; i++) {
                unsigned long long a2 = pk2(a[i], a[i]);
                #pragma unroll
                for (int q = 0; q < 4; q++) ffma2(acc2[i][q], a2, bv2[q]);
            }
        }
        __syncthreads();
    }
    // unpack -> identical epilogue (column mapping j<4 -> tx*4+j ; j>=4 -> 64+tx*4+..)
    float cs[8];
    #pragma unroll
    for (int j = 0; j < 8; j++) cs[j] = 0.f;   // filled below per j
    #pragma unroll
    for (int j = 0; j < 8; j++) {
        float gv[8];
        float s = 0.f;
        #pragma unroll
        for (int i = 0; i < 8; i++) {
            float lo, hi;
            upk2(lo, hi, acc2[i][j >> 1]);
            float aij = (j & 1) ? hi : lo;
            gv[i] = gelu_exact(aij);
            s += gv[i];
        }
        cs[j] = s;
        int ncol = (j < 4) ? (tx * 4 + j) : (64 + tx * 4 + (j - 4));
        int n = n0 + ncol;
        float* dst = &g_actsT[((size_t)b * NPROC + n) * SS + m0 + ty * 8];
        *(float4*)dst = make_float4(
            wmma::__float_to_tf32(gv[0]), wmma::__float_to_tf32(gv[1]),
            wmma::__float_to_tf32(gv[2]), wmma::__float_to_tf32(gv[3]));
        *(float4*)(dst + 4) = make_float4(
            wmma::__float_to_tf32(gv[4]), wmma::__float_to_tf32(gv[5]),
            wmma::__float_to_tf32(gv[6]), wmma::__float_to_tf32(gv[7]));
    }
    __syncthreads();
    #pragma unroll
    for (int j = 0; j < 8; j++) {
        int ncol = (j < 4) ? (tx * 4 + j) : (64 + tx * 4 + (j - 4));
        As[ty][ncol] = cs[j];
    }
    __syncthreads();
    if (tid < 128) {
        float s = 0.f;
        #pragma unroll
        for (int r = 0; r < 16; r++) s += As[r][tid];
        g_part[((size_t)b * 16 + blockIdx.x) * NPROC + n0 + tid] = s;
    }
}

// ---------------- K4: per-batch reduce + bitonic top-256 of 1024 -------------------
__global__ __launch_bounds__(512) void k_topk() {
    __shared__ float sv[NPROC];
    __shared__ int   si[NPROC];
    int b = blockIdx.x;
    int tid = threadIdx.x;
    for (int t = tid; t < NPROC; t += 512) {
        float s = 0.f;
        #pragma unroll
        for (int r = 0; r < 16; r++) s += g_part[((size_t)b * 16 + r) * NPROC + t];
        sv[t] = s; si[t] = t;
    }
    __syncthreads();
    for (int k = 2; k <= NPROC; k <<= 1) {
        for (int j = k >> 1; j > 0; j >>= 1) {
            int i = ((tid & ~(j - 1)) << 1) | (tid & (j - 1));
            int ixj = i | j;
            bool desc = ((i & k) == 0);
            float v1 = sv[i], v2 = sv[ixj];
            if ((v1 < v2) == desc) {
                sv[i] = v2; sv[ixj] = v1;
                int tmp = si[i]; si[i] = si[ixj]; si[ixj] = tmp;
            }
            __syncthreads();
        }
    }
    if (tid < KPROC) g_pidx[b * KPROC + tid] = si[tid];
}

// ---------------- K6: out = actsT_sel^T @ Ptf_sel — TF32 TC (3-stage ring) ---------
#define K6_STAGE_F 8704              // floats per stage: As 32*136 + Bs 32*136
__device__ __forceinline__ void k6_issue_stage(float* dsm, int s, int kc,
                                               const float* AT, const int* pidx,
                                               int m0, int n0, int tid) {
    float* As_ = dsm + s * K6_STAGE_F;
    float* Bs_ = As_ + 4352;
    #pragma unroll
    for (int it = 0; it < 8; it++) {
        int idx = tid + it * 128;
        int row = idx >> 5, c4 = (idx & 31) * 4;
        int nr = pidx[kc + row];
        unsigned dst = (unsigned)__cvta_generic_to_shared(&As_[row * 136 + c4]);
        const float* src = &AT[(size_t)nr * SS + m0 + c4];
        asm volatile("cp.async.cg.shared.global [%0], [%1], 16;\n" :: "r"(dst), "l"(src));
    }
    #pragma unroll
    for (int it = 0; it < 8; it++) {
        int idx = tid + it * 128;
        int row = idx >> 5, c4 = (idx & 31) * 4;
        int nr = pidx[kc + row];
        unsigned dst = (unsigned)__cvta_generic_to_shared(&Bs_[row * 136 + c4]);
        const float* src = &g_Ptf[(size_t)nr * DM + n0 + c4];
        asm volatile("cp.async.cg.shared.global [%0], [%1], 16;\n" :: "r"(dst), "l"(src));
    }
    asm volatile("cp.async.commit_group;\n" ::);
}

__global__ __launch_bounds__(128) void k_out_tc(float* __restrict__ out) {
    extern __shared__ float dsm[];
    int b = blockIdx.z;
    int m0 = blockIdx.x * 128;
    int n0 = blockIdx.y * 128;
    int tid = threadIdx.x;
    int wid = tid >> 5;
    int wm = wid & 1;
    int wn = wid >> 1;
    const float* AT = g_actsT + (size_t)b * NPROC * SS;
    const int* pidx = g_pidx + b * KPROC;

    wmma::fragment<wmma::accumulator, 16, 16, 8, float> acc[4][4];
    #pragma unroll
    for (int i = 0; i < 4; i++)
        #pragma unroll
        for (int j = 0; j < 4; j++) wmma::fill_fragment(acc[i][j], 0.0f);

    k6_issue_stage(dsm, 0, 0, AT, pidx, m0, n0, tid);
    k6_issue_stage(dsm, 1, 32, AT, pidx, m0, n0, tid);

    #pragma unroll
    for (int t = 0; t < 8; t++) {
        if (t < 7) asm volatile("cp.async.wait_group 1;\n" ::);
        else       asm volatile("cp.async.wait_group 0;\n" ::);
        __syncthreads();
        if (t + 2 < 8)
            k6_issue_stage(dsm, (t + 2) % 3, (t + 2) * 32, AT, pidx, m0, n0, tid);
        float* As_ = dsm + (t % 3) * K6_STAGE_F;
        float* Bs_ = As_ + 4352;
        #pragma unroll
        for (int ks = 0; ks < 4; ks++) {
            wmma::fragment<wmma::matrix_a, 16, 16, 8, wmma::precision::tf32,
                           wmma::col_major> af[4];
            wmma::fragment<wmma::matrix_b, 16, 16, 8, wmma::precision::tf32,
                           wmma::row_major> bf[4];
            #pragma unroll
            for (int i = 0; i < 4; i++)
                wmma::load_matrix_sync(af[i], &As_[(ks * 8) * 136 + wm * 64 + i * 16], 136);
            #pragma unroll
            for (int j = 0; j < 4; j++)
                wmma::load_matrix_sync(bf[j], &Bs_[(ks * 8) * 136 + wn * 64 + j * 16], 136);
            #pragma unroll
            for (int i = 0; i < 4; i++)
                #pragma unroll
                for (int j = 0; j < 4; j++)
                    wmma::mma_sync(acc[i][j], af[i], bf[j], acc[i][j]);
        }
    }
    #pragma unroll
    for (int i = 0; i < 4; i++)
        #pragma unroll
        for (int j = 0; j < 4; j++) {
            float* dst = out + ((size_t)(b * SS + m0 + wm * 64 + i * 16)) * DM
                             + n0 + wn * 64 + j * 16;
            wmma::store_matrix_sync(dst, acc[i][j], DM, wmma::mem_row_major);
        }
}

// ---------------- launch -----------------------------------------------------------
extern "C" void kernel_launch(void* const* d_in, const int* in_sizes, int n_in,
                              void* d_out, int out_size) {
    const float* X    = (const float*)d_in[0];   // [8,2048,128]
    const float* PW   = (const float*)d_in[1];   // [1024,256]
    const float* PO   = (const float*)d_in[2];   // [1024,1024]
    const int*   IIDX = (const int*)d_in[3];     // [8,128]

    cudaFuncSetAttribute(k_out_tc, cudaFuncAttributeMaxDynamicSharedMemorySize,
                         3 * K6_STAGE_F * 4);

    k_transpose<<<dim3(NIN / 32, NPROC / 32), dim3(32, 8)>>>(PW);
    k_gather_wg<<<BB * KIN, 256>>>(IIDX);
    k_round_P<<<(NPROC * DM / 4) / 256, 256>>>(PO);
    k_scores<<<dim3(16, 8, BB), 256>>>(X);
    k_topk<<<BB, 512>>>();
    k_out_tc<<<dim3(16, 8, BB), 128, 3 * K6_STAGE_F * 4>>>((float*)d_out);
}

// round 15
// speedup vs baseline: 1.6777x; 1.4879x over previous
#include <cuda_runtime.h>
#include <cuda_fp16.h>
#include <math.h>
#include <mma.h>

using namespace nvcuda;

#define BB 8
#define SS 2048
#define KIN 128
#define NIN 256
#define NPROC 1024
#define KPROC 256
#define DM 1024

// ---------------- scratch (device globals; no allocation allowed) ----------------
__device__ float  g_PWT[NIN * NPROC];
__device__ float  g_Wg[BB * KIN * NPROC];
__device__ float  g_part[BB * 16 * NPROC];
__device__ int    g_pidx[BB * KPROC];
__device__ __half g_actsTh[(size_t)BB * NPROC * SS]; // gelu acts, transposed, fp16
__device__ __half g_Ph[NPROC * DM];                  // process_outputs, fp16

__device__ __forceinline__ float gelu_exact(float x) {
    return 0.5f * x * (1.0f + erff(x * 0.70710678118654752f));
}

// ---- packed dual-fp32 helpers (f32x2; per-lane fp32 RN => bit-identical) ----------
__device__ __forceinline__ unsigned long long pk2(float lo, float hi) {
    unsigned long long r;
    asm("mov.b64 %0, {%1, %2};" : "=l"(r) : "f"(lo), "f"(hi));
    return r;
}
__device__ __forceinline__ void upk2(float& lo, float& hi, unsigned long long v) {
    asm("mov.b64 {%0, %1}, %2;" : "=f"(lo), "=f"(hi) : "l"(v));
}
__device__ __forceinline__ void ffma2(unsigned long long& d,
                                      unsigned long long a, unsigned long long b) {
    asm("fma.rn.f32x2 %0, %1, %2, %0;" : "+l"(d) : "l"(a), "l"(b));
}

// ---------------- K0: transpose process_weights [1024][256] -> PWT [256][1024] ----
__global__ void k_transpose(const float* __restrict__ pw) {
    __shared__ float t[32][33];
    int x = blockIdx.x * 32 + threadIdx.x;
    int y = blockIdx.y * 32 + threadIdx.y;
    #pragma unroll
    for (int i = 0; i < 32; i += 8)
        t[threadIdx.y + i][threadIdx.x] = pw[(y + i) * NIN + x];
    __syncthreads();
    int x2 = blockIdx.y * 32 + threadIdx.x;
    int y2 = blockIdx.x * 32 + threadIdx.y;
    #pragma unroll
    for (int i = 0; i < 32; i += 8)
        g_PWT[(y2 + i) * NPROC + x2] = t[threadIdx.x][threadIdx.y + i];
}

// ---------------- K1: gather Wg[b][k][:] = PWT[input_idx[b][k]][:] -----------------
__global__ void k_gather_wg(const int* __restrict__ iidx) {
    int b = blockIdx.x / KIN;
    int k = blockIdx.x % KIN;
    int c = iidx[b * KIN + k];
    const float4* src = (const float4*)&g_PWT[(size_t)c * NPROC];
    float4* dst = (float4*)&g_Wg[((size_t)b * KIN + k) * NPROC];
    dst[threadIdx.x] = src[threadIdx.x];
}

// ---------------- K1b: convert process_outputs to fp16 -----------------------------
__global__ void k_half_P(const float* __restrict__ P) {
    int idx = blockIdx.x * blockDim.x + threadIdx.x;   // over 1M/8
    float4 v0 = ((const float4*)P)[idx * 2];
    float4 v1 = ((const float4*)P)[idx * 2 + 1];
    __half2 h[4];
    h[0] = __floats2half2_rn(v0.x, v0.y);
    h[1] = __floats2half2_rn(v0.z, v0.w);
    h[2] = __floats2half2_rn(v1.x, v1.y);
    h[3] = __floats2half2_rn(v1.z, v1.w);
    *(uint4*)&g_Ph[(size_t)idx * 8] = *(const uint4*)h;
}

// ---------------- K2: GEMM1 + gelu — SIMT f32x2; vectorized a-loads ----------------
// 128x128 tile, 8x8 microtile, K-tile 32; per-lane fp32 RN, same k order ->
// scores bit-identical. Epilogue: exact colsums + fp16 acts (transposed).
__global__ __launch_bounds__(256) void k_scores(const float* __restrict__ X) {
    __shared__ float As[32][128];
    __shared__ float Bs[32][128];
    int b = blockIdx.z;
    int m0 = blockIdx.x * 128;
    int n0 = blockIdx.y * 128;
    int tid = threadIdx.x;
    int tx = tid & 15, ty = tid >> 4;
    const float* A = X + (size_t)b * SS * KIN;
    const float* Bm = g_Wg + (size_t)b * KIN * NPROC;
    unsigned long long acc2[8][4];   // lanes: (j=2q, j=2q+1)
    #pragma unroll
    for (int i = 0; i < 8; i++)
        #pragma unroll
        for (int q = 0; q < 4; q++) acc2[i][q] = 0ULL;

    for (int kc = 0; kc < KIN; kc += 32) {
        #pragma unroll
        for (int it = 0; it < 4; it++) {
            int idx = tid + it * 256;
            int row = idx >> 3, c4 = (idx & 7) * 4;
            float4 v = *(const float4*)&A[(m0 + row) * KIN + kc + c4];
            As[c4 + 0][row] = v.x; As[c4 + 1][row] = v.y;
            As[c4 + 2][row] = v.z; As[c4 + 3][row] = v.w;
        }
        #pragma unroll
        for (int it = 0; it < 4; it++) {
            int idx = tid + it * 256;
            int row = idx >> 5, c4 = (idx & 31) * 4;
            *(float4*)&Bs[row][c4] =
                *(const float4*)&Bm[(kc + row) * NPROC + n0 + c4];
        }
        __syncthreads();
        #pragma unroll
        for (int kk = 0; kk < 32; kk++) {
            float a[8], bv[8];
            *(float4*)&a[0] = *(const float4*)&As[kk][ty * 8];
            *(float4*)&a[4] = *(const float4*)&As[kk][ty * 8 + 4];
            *(float4*)&bv[0] = *(const float4*)&Bs[kk][tx * 4];
            *(float4*)&bv[4] = *(const float4*)&Bs[kk][64 + tx * 4];
            unsigned long long bv2[4];
            #pragma unroll
            for (int q = 0; q < 4; q++) bv2[q] = pk2(bv[2 * q], bv[2 * q + 1]);
            #pragma unroll
            for (int i = 0; i < 8; i++) {
                unsigned long long a2 = pk2(a[i], a[i]);
                #pragma unroll
                for (int q = 0; q < 4; q++) ffma2(acc2[i][q], a2, bv2[q]);
            }
        }
        __syncthreads();
    }
    // epilogue (column mapping j<4 -> n0+tx*4+j ; j>=4 -> n0+64+tx*4+(j-4))
    float cs[8];
    #pragma unroll
    for (int j = 0; j < 8; j++) {
        float gv[8];
        float s = 0.f;
        #pragma unroll
        for (int i = 0; i < 8; i++) {
            float lo, hi;
            upk2(lo, hi, acc2[i][j >> 1]);
            float aij = (j & 1) ? hi : lo;
            gv[i] = gelu_exact(aij);
            s += gv[i];
        }
        cs[j] = s;
        int ncol = (j < 4) ? (tx * 4 + j) : (64 + tx * 4 + (j - 4));
        int n = n0 + ncol;
        __half2 h[4];
        h[0] = __floats2half2_rn(gv[0], gv[1]);
        h[1] = __floats2half2_rn(gv[2], gv[3]);
        h[2] = __floats2half2_rn(gv[4], gv[5]);
        h[3] = __floats2half2_rn(gv[6], gv[7]);
        __half* dst = &g_actsTh[((size_t)b * NPROC + n) * SS + m0 + ty * 8];
        *(uint4*)dst = *(const uint4*)h;
    }
    __syncthreads();
    #pragma unroll
    for (int j = 0; j < 8; j++) {
        int ncol = (j < 4) ? (tx * 4 + j) : (64 + tx * 4 + (j - 4));
        As[ty][ncol] = cs[j];
    }
    __syncthreads();
    if (tid < 128) {
        float s = 0.f;
        #pragma unroll
        for (int r = 0; r < 16; r++) s += As[r][tid];
        g_part[((size_t)b * 16 + blockIdx.x) * NPROC + n0 + tid] = s;
    }
}

// ---------------- K4: per-batch reduce + bitonic top-256 of 1024 -------------------
__global__ __launch_bounds__(512) void k_topk() {
    __shared__ float sv[NPROC];
    __shared__ int   si[NPROC];
    int b = blockIdx.x;
    int tid = threadIdx.x;
    for (int t = tid; t < NPROC; t += 512) {
        float s = 0.f;
        #pragma unroll
        for (int r = 0; r < 16; r++) s += g_part[((size_t)b * 16 + r) * NPROC + t];
        sv[t] = s; si[t] = t;
    }
    __syncthreads();
    for (int k = 2; k <= NPROC; k <<= 1) {
        for (int j = k >> 1; j > 0; j >>= 1) {
            int i = ((tid & ~(j - 1)) << 1) | (tid & (j - 1));
            int ixj = i | j;
            bool desc = ((i & k) == 0);
            float v1 = sv[i], v2 = sv[ixj];
            if ((v1 < v2) == desc) {
                sv[i] = v2; sv[ixj] = v1;
                int tmp = si[i]; si[i] = si[ixj]; si[ixj] = tmp;
            }
            __syncthreads();
        }
    }
    if (tid < KPROC) g_pidx[b * KPROC + tid] = si[tid];
}

// ---------------- K6: out = actsTh_sel^T @ Ph_sel — FP16 TC, fp32 accum ------------
// M128 x N128, 128 threads (4 warps 2x2, warp tile 64x64), K-tile 32 (2 k16 mmas),
// 3-stage cp.async ring; fp16 halves smem/gmem traffic and doubles K per mma.
#define K6_PITCH 136                      // halves per smem row
#define K6_STAGE_H (2 * 32 * K6_PITCH)    // 8704 halves = 17408 B per stage
__device__ __forceinline__ void k6_issue_stage(__half* dsm, int s, int kc,
                                               const __half* AT, const int* pidx,
                                               int m0, int n0, int tid) {
    __half* As_ = dsm + s * K6_STAGE_H;
    __half* Bs_ = As_ + 32 * K6_PITCH;
    #pragma unroll
    for (int it = 0; it < 4; it++) {      // A: 32 k-rows x 128 m halves
        int idx = tid + it * 128;
        int row = idx >> 4, c8 = (idx & 15) * 8;
        int nr = pidx[kc + row];
        unsigned dst = (unsigned)__cvta_generic_to_shared(&As_[row * K6_PITCH + c8]);
        const __half* src = &AT[(size_t)nr * SS + m0 + c8];
        asm volatile("cp.async.cg.shared.global [%0], [%1], 16;\n" :: "r"(dst), "l"(src));
    }
    #pragma unroll
    for (int it = 0; it < 4; it++) {      // B: 32 k-rows x 128 n halves
        int idx = tid + it * 128;
        int row = idx >> 4, c8 = (idx & 15) * 8;
        int nr = pidx[kc + row];
        unsigned dst = (unsigned)__cvta_generic_to_shared(&Bs_[row * K6_PITCH + c8]);
        const __half* src = &g_Ph[(size_t)nr * DM + n0 + c8];
        asm volatile("cp.async.cg.shared.global [%0], [%1], 16;\n" :: "r"(dst), "l"(src));
    }
    asm volatile("cp.async.commit_group;\n" ::);
}

__global__ __launch_bounds__(128) void k_out_tc(float* __restrict__ out) {
    extern __shared__ __half dsmh[];
    int b = blockIdx.z;
    int m0 = blockIdx.x * 128;
    int n0 = blockIdx.y * 128;
    int tid = threadIdx.x;
    int wid = tid >> 5;
    int wm = wid & 1;
    int wn = wid >> 1;
    const __half* AT = g_actsTh + (size_t)b * NPROC * SS;
    const int* pidx = g_pidx + b * KPROC;

    wmma::fragment<wmma::accumulator, 16, 16, 16, float> acc[4][4];
    #pragma unroll
    for (int i = 0; i < 4; i++)
        #pragma unroll
        for (int j = 0; j < 4; j++) wmma::fill_fragment(acc[i][j], 0.0f);

    k6_issue_stage(dsmh, 0, 0, AT, pidx, m0, n0, tid);
    k6_issue_stage(dsmh, 1, 32, AT, pidx, m0, n0, tid);

    #pragma unroll
    for (int t = 0; t < 8; t++) {
        if (t < 7) asm volatile("cp.async.wait_group 1;\n" ::);
        else       asm volatile("cp.async.wait_group 0;\n" ::);
        __syncthreads();
        if (t + 2 < 8)
            k6_issue_stage(dsmh, (t + 2) % 3, (t + 2) * 32, AT, pidx, m0, n0, tid);
        __half* As_ = dsmh + (t % 3) * K6_STAGE_H;
        __half* Bs_ = As_ + 32 * K6_PITCH;
        #pragma unroll
        for (int ks = 0; ks < 2; ks++) {     // two k16 mma steps per 32-K stage
            wmma::fragment<wmma::matrix_a, 16, 16, 16, __half, wmma::col_major> af[4];
            wmma::fragment<wmma::matrix_b, 16, 16, 16, __half, wmma::row_major> bf[4];
            #pragma unroll
            for (int i = 0; i < 4; i++)
                wmma::load_matrix_sync(af[i], &As_[(ks * 16) * K6_PITCH + wm * 64 + i * 16],
                                       K6_PITCH);
            #pragma unroll
            for (int j = 0; j < 4; j++)
                wmma::load_matrix_sync(bf[j], &Bs_[(ks * 16) * K6_PITCH + wn * 64 + j * 16],
                                       K6_PITCH);
            #pragma unroll
            for (int i = 0; i < 4; i++)
                #pragma unroll
                for (int j = 0; j < 4; j++)
                    wmma::mma_sync(acc[i][j], af[i], bf[j], acc[i][j]);
        }
    }
    #pragma unroll
    for (int i = 0; i < 4; i++)
        #pragma unroll
        for (int j = 0; j < 4; j++) {
            float* dst = out + ((size_t)(b * SS + m0 + wm * 64 + i * 16)) * DM
                             + n0 + wn * 64 + j * 16;
            wmma::store_matrix_sync(dst, acc[i][j], DM, wmma::mem_row_major);
        }
}

// ---------------- launch -----------------------------------------------------------
extern "C" void kernel_launch(void* const* d_in, const int* in_sizes, int n_in,
                              void* d_out, int out_size) {
    const float* X    = (const float*)d_in[0];   // [8,2048,128]
    const float* PW   = (const float*)d_in[1];   // [1024,256]
    const float* PO   = (const float*)d_in[2];   // [1024,1024]
    const int*   IIDX = (const int*)d_in[3];     // [8,128]

    cudaFuncSetAttribute(k_out_tc, cudaFuncAttributeMaxDynamicSharedMemorySize,
                         3 * K6_STAGE_H * 2);

    k_transpose<<<dim3(NIN / 32, NPROC / 32), dim3(32, 8)>>>(PW);
    k_gather_wg<<<BB * KIN, 256>>>(IIDX);
    k_half_P<<<(NPROC * DM / 8) / 256, 256>>>(PO);
    k_scores<<<dim3(16, 8, BB), 256>>>(X);
    k_topk<<<BB, 512>>>();
    k_out_tc<<<dim3(16, 8, BB), 128, 3 * K6_STAGE_H * 2>>>((float*)d_out);
}

// round 17
// speedup vs baseline: 2.6044x; 1.5524x over previous
#include <cuda_runtime.h>
#include <cuda_fp16.h>
#include <math.h>
#include <mma.h>

using namespace nvcuda;

#define BB 8
#define SS 2048
#define KIN 128
#define NIN 256
#define NPROC 1024
#define KPROC 256
#define DM 1024

// ---------------- scratch (device globals; no allocation allowed) ----------------
__device__ float  g_PWT[NIN * NPROC];
__device__ float  g_part[BB * 16 * NPROC];
__device__ int    g_pidx[BB * KPROC];
__device__ __half g_Xh[(size_t)BB * SS * KIN];       // X split-hi (fp16)
__device__ __half g_Xl[(size_t)BB * SS * KIN];       // X split-lo (fp16 residual)
__device__ __half g_Wgh[(size_t)BB * KIN * NPROC];   // gathered W split-hi
__device__ __half g_Wgl[(size_t)BB * KIN * NPROC];   // gathered W split-lo
__device__ __half g_actsTh[(size_t)BB * NPROC * SS]; // gelu acts, transposed, fp16
__device__ __half g_Ph[NPROC * DM];                  // process_outputs, fp16

__device__ __forceinline__ float gelu_exact(float x) {
    return 0.5f * x * (1.0f + erff(x * 0.70710678118654752f));
}

// ---------------- K0: transpose process_weights [1024][256] -> PWT [256][1024] ----
__global__ void k_transpose(const float* __restrict__ pw) {
    __shared__ float t[32][33];
    int x = blockIdx.x * 32 + threadIdx.x;
    int y = blockIdx.y * 32 + threadIdx.y;
    #pragma unroll
    for (int i = 0; i < 32; i += 8)
        t[threadIdx.y + i][threadIdx.x] = pw[(y + i) * NIN + x];
    __syncthreads();
    int x2 = blockIdx.y * 32 + threadIdx.x;
    int y2 = blockIdx.x * 32 + threadIdx.y;
    #pragma unroll
    for (int i = 0; i < 32; i += 8)
        g_PWT[(y2 + i) * NPROC + x2] = t[threadIdx.x][threadIdx.y + i];
}

// ---------------- K1: gather + fp16 hi/lo split of Wg ------------------------------
__global__ void k_gather_split_wg(const int* __restrict__ iidx) {
    int b = blockIdx.x / KIN;
    int k = blockIdx.x % KIN;
    int c = iidx[b * KIN + k];
    int n4 = threadIdx.x * 4;
    float4 v = *(const float4*)&g_PWT[(size_t)c * NPROC + n4];
    __half h[4], l[4];
    float f[4] = {v.x, v.y, v.z, v.w};
    #pragma unroll
    for (int q = 0; q < 4; q++) {
        h[q] = __float2half_rn(f[q]);
        l[q] = __float2half_rn(f[q] - __half2float(h[q]));
    }
    size_t off = ((size_t)b * KIN + k) * NPROC + n4;
    *(unsigned long long*)&g_Wgh[off] = *(const unsigned long long*)h;
    *(unsigned long long*)&g_Wgl[off] = *(const unsigned long long*)l;
}

// ---------------- K1a: fp16 hi/lo split of X ---------------------------------------
__global__ void k_split_X(const float* __restrict__ X) {
    size_t idx = (size_t)blockIdx.x * blockDim.x + threadIdx.x;  // over 2M/4
    float4 v = ((const float4*)X)[idx];
    __half h[4], l[4];
    float f[4] = {v.x, v.y, v.z, v.w};
    #pragma unroll
    for (int q = 0; q < 4; q++) {
        h[q] = __float2half_rn(f[q]);
        l[q] = __float2half_rn(f[q] - __half2float(h[q]));
    }
    *(unsigned long long*)&g_Xh[idx * 4] = *(const unsigned long long*)h;
    *(unsigned long long*)&g_Xl[idx * 4] = *(const unsigned long long*)l;
}

// ---------------- K1b: convert process_outputs to fp16 -----------------------------
__global__ void k_half_P(const float* __restrict__ P) {
    int idx = blockIdx.x * blockDim.x + threadIdx.x;   // over 1M/8
    float4 v0 = ((const float4*)P)[idx * 2];
    float4 v1 = ((const float4*)P)[idx * 2 + 1];
    __half2 h[4];
    h[0] = __floats2half2_rn(v0.x, v0.y);
    h[1] = __floats2half2_rn(v0.z, v0.w);
    h[2] = __floats2half2_rn(v1.x, v1.y);
    h[3] = __floats2half2_rn(v1.z, v1.w);
    *(uint4*)&g_Ph[(size_t)idx * 8] = *(const uint4*)h;
}

// ---------------- K2: scores via split-fp16 TC GEMM --------------------------------
// acc = Xh*Wh + Xl*Wh + Xh*Wl  (fp32 accum; dropped lo*lo <= 2^-22 rel)
// M128 x N128 tile, 128 thr = 4 warps (2x2), warp tile 64x64, K-tile 32.
// 2-stage buffer, R8-proven ordering: wait -> sync -> COMPUTE -> sync -> issue.
#define S2_A_PITCH 40                       // halves per A row (32k + 8 pad)
#define S2_B_PITCH 136                      // halves per B row (128n + 8 pad)
#define S2_A_H (128 * S2_A_PITCH)           // 5120 halves per operand tile
#define S2_B_H (32 * S2_B_PITCH)            // 4352 halves per operand tile
#define S2_STAGE_H (2 * S2_A_H + 2 * S2_B_H)  // Ah+Al+Bh+Bl = 18944 halves
#define S2_EPS_PITCH 132

__device__ __forceinline__ void s2_issue_stage(__half* dsm, int s, int kc,
                                               const __half* Xh, const __half* Xl,
                                               const __half* Wh, const __half* Wl,
                                               int m0, int n0, int tid) {
    __half* Ah_ = dsm + s * S2_STAGE_H;
    __half* Al_ = Ah_ + S2_A_H;
    __half* Bh_ = Al_ + S2_A_H;
    __half* Bl_ = Bh_ + S2_B_H;
    #pragma unroll
    for (int it = 0; it < 4; it++) {        // A tiles: 128 m x 32 k halves
        int idx = tid + it * 128;
        int row = idx >> 2, c8 = (idx & 3) * 8;
        size_t src = (size_t)(m0 + row) * KIN + kc + c8;
        unsigned d0 = (unsigned)__cvta_generic_to_shared(&Ah_[row * S2_A_PITCH + c8]);
        asm volatile("cp.async.cg.shared.global [%0], [%1], 16;\n" :: "r"(d0), "l"(&Xh[src]));
        unsigned d1 = (unsigned)__cvta_generic_to_shared(&Al_[row * S2_A_PITCH + c8]);
        asm volatile("cp.async.cg.shared.global [%0], [%1], 16;\n" :: "r"(d1), "l"(&Xl[src]));
    }
    #pragma unroll
    for (int it = 0; it < 4; it++) {        // B tiles: 32 k x 128 n halves
        int idx = tid + it * 128;
        int row = idx >> 4, c8 = (idx & 15) * 8;
        size_t src = (size_t)(kc + row) * NPROC + n0 + c8;
        unsigned d0 = (unsigned)__cvta_generic_to_shared(&Bh_[row * S2_B_PITCH + c8]);
        asm volatile("cp.async.cg.shared.global [%0], [%1], 16;\n" :: "r"(d0), "l"(&Wh[src]));
        unsigned d1 = (unsigned)__cvta_generic_to_shared(&Bl_[row * S2_B_PITCH + c8]);
        asm volatile("cp.async.cg.shared.global [%0], [%1], 16;\n" :: "r"(d1), "l"(&Wl[src]));
    }
    asm volatile("cp.async.commit_group;\n" ::);
}

__global__ __launch_bounds__(128) void k_scores_tc(void) {
    extern __shared__ __half dsmh[];
    int b = blockIdx.z;
    int m0 = blockIdx.x * 128;
    int n0 = blockIdx.y * 128;
    int tid = threadIdx.x;
    int wid = tid >> 5;
    int wm = wid & 1;
    int wn = wid >> 1;
    const __half* Xh = g_Xh + (size_t)b * SS * KIN;
    const __half* Xl = g_Xl + (size_t)b * SS * KIN;
    const __half* Wh = g_Wgh + (size_t)b * KIN * NPROC;
    const __half* Wl = g_Wgl + (size_t)b * KIN * NPROC;

    wmma::fragment<wmma::accumulator, 16, 16, 16, float> acc[4][4];
    #pragma unroll
    for (int i = 0; i < 4; i++)
        #pragma unroll
        for (int j = 0; j < 4; j++) wmma::fill_fragment(acc[i][j], 0.0f);

    s2_issue_stage(dsmh, 0, 0, Xh, Xl, Wh, Wl, m0, n0, tid);
    s2_issue_stage(dsmh, 1, 32, Xh, Xl, Wh, Wl, m0, n0, tid);

    #pragma unroll
    for (int t = 0; t < 4; t++) {
        if (t < 3) asm volatile("cp.async.wait_group 1;\n" ::);
        else       asm volatile("cp.async.wait_group 0;\n" ::);
        __syncthreads();
        __half* Ah_ = dsmh + (t & 1) * S2_STAGE_H;
        __half* Al_ = Ah_ + S2_A_H;
        __half* Bh_ = Al_ + S2_A_H;
        __half* Bl_ = Bh_ + S2_B_H;
        #pragma unroll
        for (int ks = 0; ks < 2; ks++) {
            wmma::fragment<wmma::matrix_a, 16, 16, 16, __half, wmma::row_major> ah[4], al[4];
            wmma::fragment<wmma::matrix_b, 16, 16, 16, __half, wmma::row_major> bh[4], bl[4];
            #pragma unroll
            for (int i = 0; i < 4; i++)
                wmma::load_matrix_sync(ah[i], &Ah_[(wm * 64 + i * 16) * S2_A_PITCH + ks * 16],
                                       S2_A_PITCH);
            #pragma unroll
            for (int j = 0; j < 4; j++)
                wmma::load_matrix_sync(bh[j], &Bh_[(ks * 16) * S2_B_PITCH + wn * 64 + j * 16],
                                       S2_B_PITCH);
            #pragma unroll
            for (int i = 0; i < 4; i++)
                #pragma unroll
                for (int j = 0; j < 4; j++)
                    wmma::mma_sync(acc[i][j], ah[i], bh[j], acc[i][j]);
            #pragma unroll
            for (int i = 0; i < 4; i++)
                wmma::load_matrix_sync(al[i], &Al_[(wm * 64 + i * 16) * S2_A_PITCH + ks * 16],
                                       S2_A_PITCH);
            #pragma unroll
            for (int i = 0; i < 4; i++)
                #pragma unroll
                for (int j = 0; j < 4; j++)
                    wmma::mma_sync(acc[i][j], al[i], bh[j], acc[i][j]);
            #pragma unroll
            for (int j = 0; j < 4; j++)
                wmma::load_matrix_sync(bl[j], &Bl_[(ks * 16) * S2_B_PITCH + wn * 64 + j * 16],
                                       S2_B_PITCH);
            #pragma unroll
            for (int i = 0; i < 4; i++)
                #pragma unroll
                for (int j = 0; j < 4; j++)
                    wmma::mma_sync(acc[i][j], ah[i], bl[j], acc[i][j]);
        }
        __syncthreads();   // all warps done reading stage t before refilling buffer
        if (t + 2 < 4)
            s2_issue_stage(dsmh, t & 1, (t + 2) * 32, Xh, Xl, Wh, Wl, m0, n0, tid);
    }

    // epilogue: park accumulators col-major -> eps[n][m] (pitch 132 floats)
    __syncthreads();
    float* eps = (float*)dsmh;
    #pragma unroll
    for (int i = 0; i < 4; i++)
        #pragma unroll
        for (int j = 0; j < 4; j++)
            wmma::store_matrix_sync(&eps[(wn * 64 + j * 16) * S2_EPS_PITCH + wm * 64 + i * 16],
                                    acc[i][j], S2_EPS_PITCH, wmma::mem_col_major);
    __syncthreads();
    {
        int n = tid;   // 0..127
        const float* src = &eps[n * S2_EPS_PITCH];
        __half* dst = &g_actsTh[((size_t)b * NPROC + n0 + n) * SS + m0];
        float s = 0.f;
        #pragma unroll 4
        for (int c = 0; c < 16; c++) {       // 16 chunks of 8 m-values
            float4 v0 = *(const float4*)&src[c * 8];
            float4 v1 = *(const float4*)&src[c * 8 + 4];
            float g0 = gelu_exact(v0.x), g1 = gelu_exact(v0.y);
            float g2 = gelu_exact(v0.z), g3 = gelu_exact(v0.w);
            float g4 = gelu_exact(v1.x), g5 = gelu_exact(v1.y);
            float g6 = gelu_exact(v1.z), g7 = gelu_exact(v1.w);
            s += g0; s += g1; s += g2; s += g3;
            s += g4; s += g5; s += g6; s += g7;
            __half2 h[4];
            h[0] = __floats2half2_rn(g0, g1);
            h[1] = __floats2half2_rn(g2, g3);
            h[2] = __floats2half2_rn(g4, g5);
            h[3] = __floats2half2_rn(g6, g7);
            *(uint4*)&dst[c * 8] = *(const uint4*)h;
        }
        g_part[((size_t)b * 16 + blockIdx.x) * NPROC + n0 + n] = s;
    }
}

// ---------------- K4: per-batch reduce + bitonic top-256 of 1024 -------------------
__global__ __launch_bounds__(512) void k_topk() {
    __shared__ float sv[NPROC];
    __shared__ int   si[NPROC];
    int b = blockIdx.x;
    int tid = threadIdx.x;
    for (int t = tid; t < NPROC; t += 512) {
        float s = 0.f;
        #pragma unroll
        for (int r = 0; r < 16; r++) s += g_part[((size_t)b * 16 + r) * NPROC + t];
        sv[t] = s; si[t] = t;
    }
    __syncthreads();
    for (int k = 2; k <= NPROC; k <<= 1) {
        for (int j = k >> 1; j > 0; j >>= 1) {
            int i = ((tid & ~(j - 1)) << 1) | (tid & (j - 1));
            int ixj = i | j;
            bool desc = ((i & k) == 0);
            float v1 = sv[i], v2 = sv[ixj];
            if ((v1 < v2) == desc) {
                sv[i] = v2; sv[ixj] = v1;
                int tmp = si[i]; si[i] = si[ixj]; si[ixj] = tmp;
            }
            __syncthreads();
        }
    }
    if (tid < KPROC) g_pidx[b * KPROC + tid] = si[tid];
}

// ---------------- K6: out = actsTh_sel^T @ Ph_sel — FP16 TC (measured-best) --------
#define K6_PITCH 136                      // halves per smem row
#define K6_STAGE_H (2 * 32 * K6_PITCH)    // 8704 halves = 17408 B per stage
__device__ __forceinline__ void k6_issue_stage(__half* dsm, int s, int kc,
                                               const __half* AT, const int* pidx,
                                               int m0, int n0, int tid) {
    __half* As_ = dsm + s * K6_STAGE_H;
    __half* Bs_ = As_ + 32 * K6_PITCH;
    #pragma unroll
    for (int it = 0; it < 4; it++) {
        int idx = tid + it * 128;
        int row = idx >> 4, c8 = (idx & 15) * 8;
        int nr = pidx[kc + row];
        unsigned dst = (unsigned)__cvta_generic_to_shared(&As_[row * K6_PITCH + c8]);
        const __half* src = &AT[(size_t)nr * SS + m0 + c8];
        asm volatile("cp.async.cg.shared.global [%0], [%1], 16;\n" :: "r"(dst), "l"(src));
    }
    #pragma unroll
    for (int it = 0; it < 4; it++) {
        int idx = tid + it * 128;
        int row = idx >> 4, c8 = (idx & 15) * 8;
        int nr = pidx[kc + row];
        unsigned dst = (unsigned)__cvta_generic_to_shared(&Bs_[row * K6_PITCH + c8]);
        const __half* src = &g_Ph[(size_t)nr * DM + n0 + c8];
        asm volatile("cp.async.cg.shared.global [%0], [%1], 16;\n" :: "r"(dst), "l"(src));
    }
    asm volatile("cp.async.commit_group;\n" ::);
}

__global__ __launch_bounds__(128) void k_out_tc(float* __restrict__ out) {
    extern __shared__ __half dsmh[];
    int b = blockIdx.z;
    int m0 = blockIdx.x * 128;
    int n0 = blockIdx.y * 128;
    int tid = threadIdx.x;
    int wid = tid >> 5;
    int wm = wid & 1;
    int wn = wid >> 1;
    const __half* AT = g_actsTh + (size_t)b * NPROC * SS;
    const int* pidx = g_pidx + b * KPROC;

    wmma::fragment<wmma::accumulator, 16, 16, 16, float> acc[4][4];
    #pragma unroll
    for (int i = 0; i < 4; i++)
        #pragma unroll
        for (int j = 0; j < 4; j++) wmma::fill_fragment(acc[i][j], 0.0f);

    k6_issue_stage(dsmh, 0, 0, AT, pidx, m0, n0, tid);
    k6_issue_stage(dsmh, 1, 32, AT, pidx, m0, n0, tid);

    #pragma unroll
    for (int t = 0; t < 8; t++) {
        if (t < 7) asm volatile("cp.async.wait_group 1;\n" ::);
        else       asm volatile("cp.async.wait_group 0;\n" ::);
        __syncthreads();
        if (t + 2 < 8)
            k6_issue_stage(dsmh, (t + 2) % 3, (t + 2) * 32, AT, pidx, m0, n0, tid);
        __half* As_ = dsmh + (t % 3) * K6_STAGE_H;
        __half* Bs_ = As_ + 32 * K6_PITCH;
        #pragma unroll
        for (int ks = 0; ks < 2; ks++) {
            wmma::fragment<wmma::matrix_a, 16, 16, 16, __half, wmma::col_major> af[4];
            wmma::fragment<wmma::matrix_b, 16, 16, 16, __half, wmma::row_major> bf[4];
            #pragma unroll
            for (int i = 0; i < 4; i++)
                wmma::load_matrix_sync(af[i], &As_[(ks * 16) * K6_PITCH + wm * 64 + i * 16],
                                       K6_PITCH);
            #pragma unroll
            for (int j = 0; j < 4; j++)
                wmma::load_matrix_sync(bf[j], &Bs_[(ks * 16) * K6_PITCH + wn * 64 + j * 16],
                                       K6_PITCH);
            #pragma unroll
            for (int i = 0; i < 4; i++)
                #pragma unroll
                for (int j = 0; j < 4; j++)
                    wmma::mma_sync(acc[i][j], af[i], bf[j], acc[i][j]);
        }
    }
    #pragma unroll
    for (int i = 0; i < 4; i++)
        #pragma unroll
        for (int j = 0; j < 4; j++) {
            float* dst = out + ((size_t)(b * SS + m0 + wm * 64 + i * 16)) * DM
                             + n0 + wn * 64 + j * 16;
            wmma::store_matrix_sync(dst, acc[i][j], DM, wmma::mem_row_major);
        }
}

// ---------------- launch -----------------------------------------------------------
extern "C" void kernel_launch(void* const* d_in, const int* in_sizes, int n_in,
                              void* d_out, int out_size) {
    const float* X    = (const float*)d_in[0];   // [8,2048,128]
    const float* PW   = (const float*)d_in[1];   // [1024,256]
    const float* PO   = (const float*)d_in[2];   // [1024,1024]
    const int*   IIDX = (const int*)d_in[3];     // [8,128]

    cudaFuncSetAttribute(k_out_tc, cudaFuncAttributeMaxDynamicSharedMemorySize,
                         3 * K6_STAGE_H * 2);
    cudaFuncSetAttribute(k_scores_tc, cudaFuncAttributeMaxDynamicSharedMemorySize,
                         2 * S2_STAGE_H * 2);

    k_transpose<<<dim3(NIN / 32, NPROC / 32), dim3(32, 8)>>>(PW);
    k_gather_split_wg<<<BB * KIN, 256>>>(IIDX);
    k_split_X<<<(BB * SS * KIN / 4) / 256, 256>>>(X);
    k_half_P<<<(NPROC * DM / 8) / 256, 256>>>(PO);
    k_scores_tc<<<dim3(16, 8, BB), 128, 2 * S2_STAGE_H * 2>>>();
    k_topk<<<BB, 512>>>();
    k_out_tc<<<dim3(16, 8, BB), 128, 3 * K6_STAGE_H * 2>>>((float*)d_out);
}